// round 15
// baseline (speedup 1.0000x reference)
#include <cuda_runtime.h>
#include <cuda_fp16.h>
#include <cstdint>
#include <math.h>

#define NTOK  16384
#define DM    1536
#define QKVD  2304

// ---- scratch (__device__ globals; no allocations allowed) ----
__device__ __half g_xh[(size_t)NTOK * DM];
__device__ __half g_wqh[(size_t)QKVD * DM];
__device__ __half g_woh[(size_t)DM * DM];
__device__ __half g_qkvh[(size_t)NTOK * QKVD];
__device__ __half g_vT[(size_t)256 * 96 * 256];     // [bt*4+grp][d][key]
__device__ __half g_ath[(size_t)NTOK * DM];
__device__ float g_cos[1024], g_sin[1024];

// ---- helpers ----
__device__ __forceinline__ uint32_t packh2(float x, float y) {
    __half2 t = __floats2half2_rn(x, y);
    return *reinterpret_cast<uint32_t*>(&t);
}

__device__ __forceinline__ void mma_f16(float* c, uint32_t a0, uint32_t a1, uint32_t a2, uint32_t a3,
                                        uint32_t b0, uint32_t b1) {
    asm volatile(
        "mma.sync.aligned.m16n8k16.row.col.f32.f16.f16.f32 "
        "{%0,%1,%2,%3},{%4,%5,%6,%7},{%8,%9},{%0,%1,%2,%3};\n"
        : "+f"(c[0]), "+f"(c[1]), "+f"(c[2]), "+f"(c[3])
        : "r"(a0), "r"(a1), "r"(a2), "r"(a3), "r"(b0), "r"(b1));
}

__device__ __forceinline__ float ex2f(float x) {
    float r;
    asm("ex2.approx.ftz.f32 %0, %1;" : "=f"(r) : "f"(x));
    return r;
}

// ---------------------------------------------------------------------------
// fp32 -> fp16 convert
// ---------------------------------------------------------------------------
__global__ __launch_bounds__(256) void cvt_kernel(const float4* __restrict__ src,
                                                  uint32_t* __restrict__ h, int n4) {
    int i = blockIdx.x * 256 + threadIdx.x;
    if (i < n4) {
        float4 v = src[i];
        h[2 * i]     = packh2(v.x, v.y);
        h[2 * i + 1] = packh2(v.z, v.w);
    }
}

// ---------------------------------------------------------------------------
// RoPE tables
// ---------------------------------------------------------------------------
__global__ void rope_table_kernel() {
    int i = threadIdx.x;
    if (i < 1024) {
        int r = i >> 4, j = i & 15;
        int pos = (r < 32) ? r : (r < 48 ? r - 32 : r - 48);
        float inv = powf(10000.0f, -(float)j / 16.0f);
        float ang = (float)pos * inv;
        float s, c;
        sincosf(ang, &s, &c);
        g_cos[i] = c;
        g_sin[i] = s;
    }
}

// ---------------------------------------------------------------------------
// RoPE on q (scaled by log2e/sqrt(96)) and k, single fp16 plane
// ---------------------------------------------------------------------------
__global__ __launch_bounds__(256) void rope_kernel() {
    const float SC2 = 1.4426950408889634f * 0.10206207261596575f;
    int tok = blockIdx.x;
    int t  = (tok >> 8) & 31;
    int s  = tok & 255;
    int rh = s >> 4, cw = s & 15;
    __half* ph = g_qkvh + (size_t)tok * QKVD;
    for (int i = threadIdx.x; i < 960; i += 256) {
        int head = i / 48, p = i % 48;
        int chunk = p >> 4, j = p & 15;
        int col0 = (head < 16 ? head * 96 : 1536 + (head - 16) * 96) + chunk * 32 + j;
        int pos = (chunk == 0) ? t : (chunk == 1 ? 32 + rh : 48 + cw);
        float c = g_cos[pos * 16 + j], sn = g_sin[pos * 16 + j];
        float x1 = __half2float(ph[col0]);
        float x2 = __half2float(ph[col0 + 16]);
        float y1 = x1 * c - x2 * sn;
        float y2 = x2 * c + x1 * sn;
        if (head < 16) { y1 *= SC2; y2 *= SC2; }
        ph[col0]      = __float2half_rn(y1);
        ph[col0 + 16] = __float2half_rn(y2);
    }
}

// ---------------------------------------------------------------------------
// V pre-transpose: g_vT[bt*4+grp][d 0..95][key 0..255] <- g_qkvh v-section.
// 512 CTAs = bt(64) x grp(4) x half(2); 128 keys per CTA; XOR-swizzled smem.
// ---------------------------------------------------------------------------
__global__ __launch_bounds__(256) void vT_kernel() {
    __shared__ uint32_t sm32[128 * 64];   // 32 KB, 16 uint4-slots per key row
    const int tid = threadIdx.x;
    const int cta = blockIdx.x;
    const int half = cta & 1;
    const int grp = (cta >> 1) & 3;
    const int bt = cta >> 3;
    const size_t tokbase = (size_t)bt * 256 + half * 128;

    #pragma unroll
    for (int it = 0; it < 6; it++) {
        int u = tid + it * 256;
        int key = u / 12, c8 = u % 12;
        uint4 v = *(const uint4*)(g_qkvh + (tokbase + key) * QKVD + 1920 + grp * 96 + c8 * 8);
        int slot = c8 ^ ((key & 7) ^ ((key >> 3) & 7));
        *(uint4*)&sm32[key * 64 + slot * 4] = v;
    }
    __syncthreads();

    __half* dst = g_vT + ((size_t)(bt * 4 + grp)) * 24576 + half * 128;
    #pragma unroll
    for (int it = 0; it < 3; it++) {
        int u = tid + it * 256;
        int k8 = u & 15, c = u >> 4;
        int c4 = c >> 2, cm = c & 3;
        uint32_t w[8];
        #pragma unroll
        for (int i = 0; i < 8; i++) {
            int key = k8 * 8 + i;
            int slot = c4 ^ ((key & 7) ^ ((key >> 3) & 7));
            w[i] = sm32[key * 64 + slot * 4 + cm];
        }
        uint32_t outlo[4], outhi[4];
        #pragma unroll
        for (int i = 0; i < 4; i++) {
            outlo[i] = __byte_perm(w[2 * i], w[2 * i + 1], 0x5410);
            outhi[i] = __byte_perm(w[2 * i], w[2 * i + 1], 0x7632);
        }
        *(uint4*)(dst + (2 * c) * 256 + k8 * 8)     = *(uint4*)outlo;
        *(uint4*)(dst + (2 * c + 1) * 256 + k8 * 8) = *(uint4*)outhi;
    }
}

// ---------------------------------------------------------------------------
// Plain FP16 GEMM: C = Ah*Bh. OUT16=1 -> fp16 output; 0 -> fp32.
// 128x128 tile, BK=32, 8 warps, warp tile 64x32, m16n8k16, reg-prefetch.
// ---------------------------------------------------------------------------
template<int OUT16>
__global__ __launch_bounds__(256) void gemm_h1(
    const __half* __restrict__ Ah,
    const __half* __restrict__ Bh,
    float* __restrict__ C, __half* __restrict__ Ch,
    int M, int N, int K)
{
    __shared__ __half sAh[128 * 40], sBh[128 * 40];

    const int tid = threadIdx.x, warp = tid >> 5, lane = tid & 31;
    const int g = lane >> 2, tg = lane & 3;
    const int m0 = blockIdx.y * 128, n0 = blockIdx.x * 128;
    const int wm = (warp >> 2) * 64, wn = (warp & 3) * 32;
    const int lrow = tid >> 1, lcol = (tid & 1) * 16;

    float acc[4][4][4];
    #pragma unroll
    for (int i = 0; i < 4; i++)
        #pragma unroll
        for (int j = 0; j < 4; j++)
            #pragma unroll
            for (int e = 0; e < 4; e++) acc[i][j][e] = 0.f;

    const __half* gAh = Ah + (size_t)(m0 + lrow) * K + lcol;
    const __half* gBh = Bh + (size_t)(n0 + lrow) * K + lcol;

    uint4 pah[2], pbh[2];
    #define LD8(kt) do { \
        pah[0] = *(const uint4*)(gAh + (kt));     pah[1] = *(const uint4*)(gAh + (kt) + 8); \
        pbh[0] = *(const uint4*)(gBh + (kt));     pbh[1] = *(const uint4*)(gBh + (kt) + 8); \
    } while (0)

    LD8(0);

    const uint32_t* A32h = (const uint32_t*)sAh;
    const uint32_t* B32h = (const uint32_t*)sBh;

    for (int kt = 0; kt < K; kt += 32) {
        *(uint4*)(sAh + lrow * 40 + lcol) = pah[0]; *(uint4*)(sAh + lrow * 40 + lcol + 8) = pah[1];
        *(uint4*)(sBh + lrow * 40 + lcol) = pbh[0]; *(uint4*)(sBh + lrow * 40 + lcol + 8) = pbh[1];
        __syncthreads();
        if (kt + 32 < K) LD8(kt + 32);

        #pragma unroll
        for (int ks = 0; ks < 2; ks++) {
            uint32_t fah[4][4];
            #pragma unroll
            for (int i = 0; i < 4; i++) {
                int r = (wm + i * 16 + g) * 20 + ks * 8 + tg;
                int r8 = r + 160;
                fah[i][0] = A32h[r]; fah[i][1] = A32h[r8]; fah[i][2] = A32h[r + 4]; fah[i][3] = A32h[r8 + 4];
            }
            #pragma unroll
            for (int j = 0; j < 4; j++) {
                int nb = (wn + j * 8 + g) * 20 + ks * 8 + tg;
                uint32_t bh0 = B32h[nb], bh1 = B32h[nb + 4];
                #pragma unroll
                for (int i = 0; i < 4; i++)
                    mma_f16(acc[i][j], fah[i][0], fah[i][1], fah[i][2], fah[i][3], bh0, bh1);
            }
        }
        __syncthreads();
    }
    #undef LD8

    #pragma unroll
    for (int i = 0; i < 4; i++)
        #pragma unroll
        for (int j = 0; j < 4; j++) {
            int row = m0 + wm + i * 16 + g;
            int col = n0 + wn + j * 8 + 2 * tg;
            if (OUT16) {
                *(uint32_t*)(Ch + (size_t)row * N + col)       = packh2(acc[i][j][0], acc[i][j][1]);
                *(uint32_t*)(Ch + (size_t)(row + 8) * N + col) = packh2(acc[i][j][2], acc[i][j][3]);
            } else {
                *(float2*)(C + (size_t)row * N + col)       = make_float2(acc[i][j][0], acc[i][j][1]);
                *(float2*)(C + (size_t)(row + 8) * N + col) = make_float2(acc[i][j][2], acc[i][j][3]);
            }
        }
}

// ---------------------------------------------------------------------------
// Attention: CTA = (b,t,head,64-query tile), 128 threads (4 warps x 16 rows).
// Flash-style, no-max f32 ex2 softmax, pure fp16 matmuls (f32 accum).
// V read pre-transposed from g_vT (plain uint4 fills, no in-CTA transpose).
// ---------------------------------------------------------------------------
__global__ __launch_bounds__(128) void attn_kernel() {
    extern __shared__ __half smb[];
    __half* Qh = smb;                 // [64][120]
    __half* Kh = Qh + 7680;           // [64][120]
    __half* Vh = Kh + 7680;           // [96][72]  (d-major, pre-transposed)

    const int tid = threadIdx.x, warp = tid >> 5, lane = tid & 31;
    const int g = lane >> 2, tg = lane & 3;
    const int bid = blockIdx.x;
    const int qt = bid & 3, h = (bid >> 2) & 15, bt = bid >> 6, grp = h >> 2;
    const size_t tokbase = (size_t)bt * 256;
    const __half* vsrc = g_vT + ((size_t)(bt * 4 + grp)) * 24576;

    #pragma unroll
    for (int t = 0; t < 6; t++) {
        int u = tid + t * 128;
        int row = u / 12, c8 = u % 12;
        size_t gb = (tokbase + qt * 64 + row) * QKVD + h * 96 + c8 * 8;
        *(uint4*)(Qh + row * 120 + c8 * 8) = *(const uint4*)(g_qkvh + gb);
    }

    const uint32_t* Q32 = (const uint32_t*)Qh;
    const uint32_t* K32 = (const uint32_t*)Kh;
    const uint32_t* V32 = (const uint32_t*)Vh;

    float acc[12][4];
    #pragma unroll
    for (int j = 0; j < 12; j++)
        #pragma unroll
        for (int e = 0; e < 4; e++) acc[j][e] = 0.f;
    float rs0 = 0.f, rs1 = 0.f;

    for (int c = 0; c < 4; c++) {
        #pragma unroll
        for (int t = 0; t < 6; t++) {
            int u = tid + t * 128;
            int row = u / 12, c8 = u % 12;
            size_t gb = (tokbase + c * 64 + row) * QKVD + 1536 + grp * 96 + c8 * 8;
            *(uint4*)(Kh + row * 120 + c8 * 8) = *(const uint4*)(g_qkvh + gb);
        }
        #pragma unroll
        for (int t = 0; t < 6; t++) {
            int u = tid + t * 128;
            int d = u >> 3, k8 = u & 7;
            *(uint4*)(Vh + d * 72 + k8 * 8) = *(const uint4*)(vsrc + d * 256 + c * 64 + k8 * 8);
        }
        __syncthreads();

        float s[8][4];
        #pragma unroll
        for (int j = 0; j < 8; j++)
            #pragma unroll
            for (int e = 0; e < 4; e++) s[j][e] = 0.f;

        #pragma unroll
        for (int ks = 0; ks < 6; ks++) {
            int r = (warp * 16 + g) * 60 + ks * 8 + tg;
            int r8 = r + 480;
            uint32_t a0 = Q32[r], a1 = Q32[r8], a2 = Q32[r + 4], a3 = Q32[r8 + 4];
            #pragma unroll
            for (int j = 0; j < 8; j++) {
                int nb = (j * 8 + g) * 60 + ks * 8 + tg;
                uint32_t b0 = K32[nb], b1 = K32[nb + 4];
                mma_f16(s[j], a0, a1, a2, a3, b0, b1);
            }
        }

        #pragma unroll
        for (int j = 0; j < 8; j++) {
            s[j][0] = ex2f(s[j][0]); s[j][1] = ex2f(s[j][1]);
            s[j][2] = ex2f(s[j][2]); s[j][3] = ex2f(s[j][3]);
            rs0 += s[j][0] + s[j][1];
            rs1 += s[j][2] + s[j][3];
        }

        #pragma unroll
        for (int kk = 0; kk < 4; kk++) {
            uint32_t A0 = packh2(s[2 * kk][0],     s[2 * kk][1]);
            uint32_t A1 = packh2(s[2 * kk][2],     s[2 * kk][3]);
            uint32_t A2 = packh2(s[2 * kk + 1][0], s[2 * kk + 1][1]);
            uint32_t A3 = packh2(s[2 * kk + 1][2], s[2 * kk + 1][3]);
            #pragma unroll
            for (int j = 0; j < 12; j++) {
                int vb = (j * 8 + g) * 36 + kk * 8 + tg;
                uint32_t b0 = V32[vb], b1 = V32[vb + 4];
                mma_f16(acc[j], A0, A1, A2, A3, b0, b1);
            }
        }
        __syncthreads();
    }

    rs0 += __shfl_xor_sync(0xffffffffu, rs0, 1);
    rs0 += __shfl_xor_sync(0xffffffffu, rs0, 2);
    rs1 += __shfl_xor_sync(0xffffffffu, rs1, 1);
    rs1 += __shfl_xor_sync(0xffffffffu, rs1, 2);
    float i0 = 1.f / rs0, i1 = 1.f / rs1;

    int tok0 = bt * 256 + qt * 64 + warp * 16 + g;
    #pragma unroll
    for (int j = 0; j < 12; j++) {
        int col = h * 96 + j * 8 + 2 * tg;
        *(uint32_t*)(g_ath + (size_t)tok0 * DM + col)       = packh2(acc[j][0] * i0, acc[j][1] * i0);
        *(uint32_t*)(g_ath + (size_t)(tok0 + 8) * DM + col) = packh2(acc[j][2] * i1, acc[j][3] * i1);
    }
}

// ---------------------------------------------------------------------------
extern "C" void kernel_launch(void* const* d_in, const int* in_sizes, int n_in,
                              void* d_out, int out_size) {
    (void)in_sizes; (void)n_in; (void)out_size;
    const float* x     = (const float*)d_in[0];
    const float* w_qkv = (const float*)d_in[2];
    const float* w_o   = (const float*)d_in[3];
    float* out = (float*)d_out;

    __half *xh, *wqh, *woh, *qkvh, *ath;
    cudaGetSymbolAddress((void**)&xh, g_xh);
    cudaGetSymbolAddress((void**)&wqh, g_wqh);
    cudaGetSymbolAddress((void**)&woh, g_woh);
    cudaGetSymbolAddress((void**)&qkvh, g_qkvh);
    cudaGetSymbolAddress((void**)&ath, g_ath);

    cudaFuncSetAttribute(attn_kernel, cudaFuncAttributeMaxDynamicSharedMemorySize, 44544);

    rope_table_kernel<<<1, 1024>>>();
    cvt_kernel<<<24576, 256>>>((const float4*)x,     (uint32_t*)xh,  6291456);
    cvt_kernel<<<3456,  256>>>((const float4*)w_qkv, (uint32_t*)wqh, 884736);
    cvt_kernel<<<2304,  256>>>((const float4*)w_o,   (uint32_t*)woh, 589824);

    dim3 g1(QKVD / 128, NTOK / 128);
    gemm_h1<1><<<g1, 256>>>(xh, wqh, nullptr, qkvh, NTOK, QKVD, DM);

    rope_kernel<<<NTOK, 256>>>();
    vT_kernel<<<512, 256>>>();

    attn_kernel<<<4096, 128, 44544>>>();

    dim3 g2(DM / 128, NTOK / 128);
    gemm_h1<0><<<g2, 256>>>(ath, woh, out, nullptr, NTOK, DM, DM);
}

// round 16
// speedup vs baseline: 1.4268x; 1.4268x over previous
#include <cuda_runtime.h>
#include <cuda_fp16.h>
#include <cstdint>
#include <math.h>

#define NTOK  16384
#define DM    1536
#define QKVD  2304

// ---- scratch (__device__ globals; no allocations allowed) ----
__device__ __half g_xh[(size_t)NTOK * DM];
__device__ __half g_wqh[(size_t)QKVD * DM];
__device__ __half g_woh[(size_t)DM * DM];
__device__ __half g_qkvh[(size_t)NTOK * QKVD];
__device__ __half g_ath[(size_t)NTOK * DM];
__device__ float g_cos[1024], g_sin[1024];

// ---- helpers ----
__device__ __forceinline__ uint32_t packh2(float x, float y) {
    __half2 t = __floats2half2_rn(x, y);
    return *reinterpret_cast<uint32_t*>(&t);
}

__device__ __forceinline__ void mma_f16(float* c, uint32_t a0, uint32_t a1, uint32_t a2, uint32_t a3,
                                        uint32_t b0, uint32_t b1) {
    asm volatile(
        "mma.sync.aligned.m16n8k16.row.col.f32.f16.f16.f32 "
        "{%0,%1,%2,%3},{%4,%5,%6,%7},{%8,%9},{%0,%1,%2,%3};\n"
        : "+f"(c[0]), "+f"(c[1]), "+f"(c[2]), "+f"(c[3])
        : "r"(a0), "r"(a1), "r"(a2), "r"(a3), "r"(b0), "r"(b1));
}

__device__ __forceinline__ float ex2f(float x) {
    float r;
    asm("ex2.approx.ftz.f32 %0, %1;" : "=f"(r) : "f"(x));
    return r;
}

// ---------------------------------------------------------------------------
// fp32 -> fp16 convert
// ---------------------------------------------------------------------------
__global__ __launch_bounds__(256) void cvt_kernel(const float4* __restrict__ src,
                                                  uint32_t* __restrict__ h, int n4) {
    int i = blockIdx.x * 256 + threadIdx.x;
    if (i < n4) {
        float4 v = src[i];
        h[2 * i]     = packh2(v.x, v.y);
        h[2 * i + 1] = packh2(v.z, v.w);
    }
}

// ---------------------------------------------------------------------------
// RoPE tables
// ---------------------------------------------------------------------------
__global__ void rope_table_kernel() {
    int i = threadIdx.x;
    if (i < 1024) {
        int r = i >> 4, j = i & 15;
        int pos = (r < 32) ? r : (r < 48 ? r - 32 : r - 48);
        float inv = powf(10000.0f, -(float)j / 16.0f);
        float ang = (float)pos * inv;
        float s, c;
        sincosf(ang, &s, &c);
        g_cos[i] = c;
        g_sin[i] = s;
    }
}

// ---------------------------------------------------------------------------
// RoPE on q (scaled by log2e/sqrt(96)) and k, single fp16 plane
// ---------------------------------------------------------------------------
__global__ __launch_bounds__(256) void rope_kernel() {
    const float SC2 = 1.4426950408889634f * 0.10206207261596575f;
    int tok = blockIdx.x;
    int t  = (tok >> 8) & 31;
    int s  = tok & 255;
    int rh = s >> 4, cw = s & 15;
    __half* ph = g_qkvh + (size_t)tok * QKVD;
    for (int i = threadIdx.x; i < 960; i += 256) {
        int head = i / 48, p = i % 48;
        int chunk = p >> 4, j = p & 15;
        int col0 = (head < 16 ? head * 96 : 1536 + (head - 16) * 96) + chunk * 32 + j;
        int pos = (chunk == 0) ? t : (chunk == 1 ? 32 + rh : 48 + cw);
        float c = g_cos[pos * 16 + j], sn = g_sin[pos * 16 + j];
        float x1 = __half2float(ph[col0]);
        float x2 = __half2float(ph[col0 + 16]);
        float y1 = x1 * c - x2 * sn;
        float y2 = x2 * c + x1 * sn;
        if (head < 16) { y1 *= SC2; y2 *= SC2; }
        ph[col0]      = __float2half_rn(y1);
        ph[col0 + 16] = __float2half_rn(y2);
    }
}

// ---------------------------------------------------------------------------
// Plain FP16 GEMM: C = Ah*Bh. OUT16=1 -> fp16 output; 0 -> fp32.
// 128x128 tile, BK=32, 8 warps, warp tile 64x32, m16n8k16, reg-prefetch.
// ---------------------------------------------------------------------------
template<int OUT16>
__global__ __launch_bounds__(256) void gemm_h1(
    const __half* __restrict__ Ah,
    const __half* __restrict__ Bh,
    float* __restrict__ C, __half* __restrict__ Ch,
    int M, int N, int K)
{
    __shared__ __half sAh[128 * 40], sBh[128 * 40];

    const int tid = threadIdx.x, warp = tid >> 5, lane = tid & 31;
    const int g = lane >> 2, tg = lane & 3;
    const int m0 = blockIdx.y * 128, n0 = blockIdx.x * 128;
    const int wm = (warp >> 2) * 64, wn = (warp & 3) * 32;
    const int lrow = tid >> 1, lcol = (tid & 1) * 16;

    float acc[4][4][4];
    #pragma unroll
    for (int i = 0; i < 4; i++)
        #pragma unroll
        for (int j = 0; j < 4; j++)
            #pragma unroll
            for (int e = 0; e < 4; e++) acc[i][j][e] = 0.f;

    const __half* gAh = Ah + (size_t)(m0 + lrow) * K + lcol;
    const __half* gBh = Bh + (size_t)(n0 + lrow) * K + lcol;

    uint4 pah[2], pbh[2];
    #define LD8(kt) do { \
        pah[0] = *(const uint4*)(gAh + (kt));     pah[1] = *(const uint4*)(gAh + (kt) + 8); \
        pbh[0] = *(const uint4*)(gBh + (kt));     pbh[1] = *(const uint4*)(gBh + (kt) + 8); \
    } while (0)

    LD8(0);

    const uint32_t* A32h = (const uint32_t*)sAh;
    const uint32_t* B32h = (const uint32_t*)sBh;

    for (int kt = 0; kt < K; kt += 32) {
        *(uint4*)(sAh + lrow * 40 + lcol) = pah[0]; *(uint4*)(sAh + lrow * 40 + lcol + 8) = pah[1];
        *(uint4*)(sBh + lrow * 40 + lcol) = pbh[0]; *(uint4*)(sBh + lrow * 40 + lcol + 8) = pbh[1];
        __syncthreads();
        if (kt + 32 < K) LD8(kt + 32);

        #pragma unroll
        for (int ks = 0; ks < 2; ks++) {
            uint32_t fah[4][4];
            #pragma unroll
            for (int i = 0; i < 4; i++) {
                int r = (wm + i * 16 + g) * 20 + ks * 8 + tg;
                int r8 = r + 160;
                fah[i][0] = A32h[r]; fah[i][1] = A32h[r8]; fah[i][2] = A32h[r + 4]; fah[i][3] = A32h[r8 + 4];
            }
            #pragma unroll
            for (int j = 0; j < 4; j++) {
                int nb = (wn + j * 8 + g) * 20 + ks * 8 + tg;
                uint32_t bh0 = B32h[nb], bh1 = B32h[nb + 4];
                #pragma unroll
                for (int i = 0; i < 4; i++)
                    mma_f16(acc[i][j], fah[i][0], fah[i][1], fah[i][2], fah[i][3], bh0, bh1);
            }
        }
        __syncthreads();
    }
    #undef LD8

    #pragma unroll
    for (int i = 0; i < 4; i++)
        #pragma unroll
        for (int j = 0; j < 4; j++) {
            int row = m0 + wm + i * 16 + g;
            int col = n0 + wn + j * 8 + 2 * tg;
            if (OUT16) {
                *(uint32_t*)(Ch + (size_t)row * N + col)       = packh2(acc[i][j][0], acc[i][j][1]);
                *(uint32_t*)(Ch + (size_t)(row + 8) * N + col) = packh2(acc[i][j][2], acc[i][j][3]);
            } else {
                *(float2*)(C + (size_t)row * N + col)       = make_float2(acc[i][j][0], acc[i][j][1]);
                *(float2*)(C + (size_t)(row + 8) * N + col) = make_float2(acc[i][j][2], acc[i][j][3]);
            }
        }
}

// ---------------------------------------------------------------------------
// Attention: CTA = (b,t,head,64-query tile), 128 threads (4 warps x 16 rows).
// Flash-style, no-max f32 ex2 softmax, pure fp16 matmuls (f32 accum):
//   scores = Qh*Kh ;  out = Ph*Vh.
// ---------------------------------------------------------------------------
__global__ __launch_bounds__(128) void attn_kernel() {
    extern __shared__ __half smb[];
    __half* Qh = smb;                 // [64][120]
    __half* Kh = Qh + 7680;           // [64][120]
    __half* Vh = Kh + 7680;           // transposed [96][72]

    const int tid = threadIdx.x, warp = tid >> 5, lane = tid & 31;
    const int g = lane >> 2, tg = lane & 3;
    const int bid = blockIdx.x;
    const int qt = bid & 3, h = (bid >> 2) & 15, bt = bid >> 6, grp = h >> 2;
    const size_t tokbase = (size_t)bt * 256;

    #pragma unroll
    for (int t = 0; t < 6; t++) {
        int u = tid + t * 128;
        int row = u / 12, c8 = u % 12;
        size_t gb = (tokbase + qt * 64 + row) * QKVD + h * 96 + c8 * 8;
        *(uint4*)(Qh + row * 120 + c8 * 8) = *(const uint4*)(g_qkvh + gb);
    }

    const uint32_t* Q32 = (const uint32_t*)Qh;
    const uint32_t* K32 = (const uint32_t*)Kh;
    const uint32_t* V32 = (const uint32_t*)Vh;

    float acc[12][4];
    #pragma unroll
    for (int j = 0; j < 12; j++)
        #pragma unroll
        for (int e = 0; e < 4; e++) acc[j][e] = 0.f;
    float rs0 = 0.f, rs1 = 0.f;

    for (int c = 0; c < 4; c++) {
        #pragma unroll
        for (int t = 0; t < 6; t++) {
            int u = tid + t * 128;
            int row = u / 12, c8 = u % 12;
            size_t gb = (tokbase + c * 64 + row) * QKVD + 1536 + grp * 96 + c8 * 8;
            *(uint4*)(Kh + row * 120 + c8 * 8) = *(const uint4*)(g_qkvh + gb);
        }
        #pragma unroll
        for (int t = 0; t < 24; t++) {
            int u = tid + t * 128;
            int key = u / 48, d = (u % 48) * 2;
            size_t gb = (tokbase + c * 64 + key) * QKVD + 1920 + grp * 96 + d;
            __half2 ph = *(const __half2*)(g_qkvh + gb);
            Vh[d * 72 + key] = __low2half(ph);  Vh[(d + 1) * 72 + key] = __high2half(ph);
        }
        __syncthreads();

        float s[8][4];
        #pragma unroll
        for (int j = 0; j < 8; j++)
            #pragma unroll
            for (int e = 0; e < 4; e++) s[j][e] = 0.f;

        #pragma unroll
        for (int ks = 0; ks < 6; ks++) {
            int r = (warp * 16 + g) * 60 + ks * 8 + tg;
            int r8 = r + 480;
            uint32_t a0 = Q32[r], a1 = Q32[r8], a2 = Q32[r + 4], a3 = Q32[r8 + 4];
            #pragma unroll
            for (int j = 0; j < 8; j++) {
                int nb = (j * 8 + g) * 60 + ks * 8 + tg;
                uint32_t b0 = K32[nb], b1 = K32[nb + 4];
                mma_f16(s[j], a0, a1, a2, a3, b0, b1);
            }
        }

        #pragma unroll
        for (int j = 0; j < 8; j++) {
            s[j][0] = ex2f(s[j][0]); s[j][1] = ex2f(s[j][1]);
            s[j][2] = ex2f(s[j][2]); s[j][3] = ex2f(s[j][3]);
            rs0 += s[j][0] + s[j][1];
            rs1 += s[j][2] + s[j][3];
        }

        #pragma unroll
        for (int kk = 0; kk < 4; kk++) {
            uint32_t A0 = packh2(s[2 * kk][0],     s[2 * kk][1]);
            uint32_t A1 = packh2(s[2 * kk][2],     s[2 * kk][3]);
            uint32_t A2 = packh2(s[2 * kk + 1][0], s[2 * kk + 1][1]);
            uint32_t A3 = packh2(s[2 * kk + 1][2], s[2 * kk + 1][3]);
            #pragma unroll
            for (int j = 0; j < 12; j++) {
                int vb = (j * 8 + g) * 36 + kk * 8 + tg;
                uint32_t b0 = V32[vb], b1 = V32[vb + 4];
                mma_f16(acc[j], A0, A1, A2, A3, b0, b1);
            }
        }
        __syncthreads();
    }

    rs0 += __shfl_xor_sync(0xffffffffu, rs0, 1);
    rs0 += __shfl_xor_sync(0xffffffffu, rs0, 2);
    rs1 += __shfl_xor_sync(0xffffffffu, rs1, 1);
    rs1 += __shfl_xor_sync(0xffffffffu, rs1, 2);
    float i0 = 1.f / rs0, i1 = 1.f / rs1;

    int tok0 = bt * 256 + qt * 64 + warp * 16 + g;
    #pragma unroll
    for (int j = 0; j < 12; j++) {
        int col = h * 96 + j * 8 + 2 * tg;
        *(uint32_t*)(g_ath + (size_t)tok0 * DM + col)       = packh2(acc[j][0] * i0, acc[j][1] * i0);
        *(uint32_t*)(g_ath + (size_t)(tok0 + 8) * DM + col) = packh2(acc[j][2] * i1, acc[j][3] * i1);
    }
}

// ---------------------------------------------------------------------------
extern "C" void kernel_launch(void* const* d_in, const int* in_sizes, int n_in,
                              void* d_out, int out_size) {
    (void)in_sizes; (void)n_in; (void)out_size;
    const float* x     = (const float*)d_in[0];
    const float* w_qkv = (const float*)d_in[2];
    const float* w_o   = (const float*)d_in[3];
    float* out = (float*)d_out;

    __half *xh, *wqh, *woh, *qkvh, *ath;
    cudaGetSymbolAddress((void**)&xh, g_xh);
    cudaGetSymbolAddress((void**)&wqh, g_wqh);
    cudaGetSymbolAddress((void**)&woh, g_woh);
    cudaGetSymbolAddress((void**)&qkvh, g_qkvh);
    cudaGetSymbolAddress((void**)&ath, g_ath);

    cudaFuncSetAttribute(attn_kernel, cudaFuncAttributeMaxDynamicSharedMemorySize, 44544);

    rope_table_kernel<<<1, 1024>>>();
    cvt_kernel<<<24576, 256>>>((const float4*)x,     (uint32_t*)xh,  6291456);
    cvt_kernel<<<3456,  256>>>((const float4*)w_qkv, (uint32_t*)wqh, 884736);
    cvt_kernel<<<2304,  256>>>((const float4*)w_o,   (uint32_t*)woh, 589824);

    dim3 g1(QKVD / 128, NTOK / 128);
    gemm_h1<1><<<g1, 256>>>(xh, wqh, nullptr, qkvh, NTOK, QKVD, DM);

    rope_kernel<<<NTOK, 256>>>();

    attn_kernel<<<4096, 128, 44544>>>();

    dim3 g2(DM / 128, NTOK / 128);
    gemm_h1<0><<<g2, 256>>>(ath, woh, out, nullptr, NTOK, DM, DM);
}

// round 17
// speedup vs baseline: 1.4615x; 1.0243x over previous
#include <cuda_runtime.h>
#include <cuda_fp16.h>
#include <cstdint>
#include <math.h>

#define NTOK  16384
#define DM    1536
#define QKVD  2304

// ---- scratch (__device__ globals; no allocations allowed) ----
__device__ __half g_xh[(size_t)NTOK * DM];
__device__ __half g_wqh[(size_t)QKVD * DM];
__device__ __half g_woh[(size_t)DM * DM];
__device__ __half g_qkvh[(size_t)NTOK * QKVD];
__device__ __half g_ath[(size_t)NTOK * DM];
__device__ float g_cos[1024], g_sin[1024];

// ---- helpers ----
__device__ __forceinline__ uint32_t packh2(float x, float y) {
    __half2 t = __floats2half2_rn(x, y);
    return *reinterpret_cast<uint32_t*>(&t);
}

__device__ __forceinline__ void mma_f16(float* c, uint32_t a0, uint32_t a1, uint32_t a2, uint32_t a3,
                                        uint32_t b0, uint32_t b1) {
    asm volatile(
        "mma.sync.aligned.m16n8k16.row.col.f32.f16.f16.f32 "
        "{%0,%1,%2,%3},{%4,%5,%6,%7},{%8,%9},{%0,%1,%2,%3};\n"
        : "+f"(c[0]), "+f"(c[1]), "+f"(c[2]), "+f"(c[3])
        : "r"(a0), "r"(a1), "r"(a2), "r"(a3), "r"(b0), "r"(b1));
}

__device__ __forceinline__ float ex2f(float x) {
    float r;
    asm("ex2.approx.ftz.f32 %0, %1;" : "=f"(r) : "f"(x));
    return r;
}

// ---------------------------------------------------------------------------
// fp32 -> fp16 convert
// ---------------------------------------------------------------------------
__global__ __launch_bounds__(256) void cvt_kernel(const float4* __restrict__ src,
                                                  uint32_t* __restrict__ h, int n4) {
    int i = blockIdx.x * 256 + threadIdx.x;
    if (i < n4) {
        float4 v = src[i];
        h[2 * i]     = packh2(v.x, v.y);
        h[2 * i + 1] = packh2(v.z, v.w);
    }
}

// ---------------------------------------------------------------------------
// RoPE tables: rows 0..31 = t, 32..47 = h, 48..63 = w; 16 freqs each
// ---------------------------------------------------------------------------
__global__ void rope_table_kernel() {
    int i = threadIdx.x;
    if (i < 1024) {
        int r = i >> 4, j = i & 15;
        int pos = (r < 32) ? r : (r < 48 ? r - 32 : r - 48);
        float inv = powf(10000.0f, -(float)j / 16.0f);
        float ang = (float)pos * inv;
        float s, c;
        sincosf(ang, &s, &c);
        g_cos[i] = c;
        g_sin[i] = s;
    }
}

// ---------------------------------------------------------------------------
// Plain FP16 GEMM: C = Ah*Bh.
// OUT16=1 (qkv proj): fp16 output with FUSED RoPE on q/k head columns
//   (q additionally scaled by log2e/sqrt(96)); v columns pass through.
// OUT16=0 (o proj): fp32 output.
// 128x128 tile, BK=32, 8 warps, warp tile 64x32, m16n8k16, reg-prefetch.
//
// RoPE fusion layout fact: each warp's 32-col block (wn) is exactly one
// (head, chunk) since head*96 + chunk*32 is 32-aligned; the rotation pair
// (col, col+16) maps to (acc[i][0],acc[i][2]) and (acc[i][1],acc[i][3])
// at identical element slots -> thread-local rotation.
// ---------------------------------------------------------------------------
template<int OUT16>
__global__ __launch_bounds__(256) void gemm_h1(
    const __half* __restrict__ Ah,
    const __half* __restrict__ Bh,
    float* __restrict__ C, __half* __restrict__ Ch,
    int M, int N, int K)
{
    __shared__ __half sAh[128 * 40], sBh[128 * 40];

    const int tid = threadIdx.x, warp = tid >> 5, lane = tid & 31;
    const int g = lane >> 2, tg = lane & 3;
    const int m0 = blockIdx.y * 128, n0 = blockIdx.x * 128;
    const int wm = (warp >> 2) * 64, wn = (warp & 3) * 32;
    const int lrow = tid >> 1, lcol = (tid & 1) * 16;

    float acc[4][4][4];
    #pragma unroll
    for (int i = 0; i < 4; i++)
        #pragma unroll
        for (int j = 0; j < 4; j++)
            #pragma unroll
            for (int e = 0; e < 4; e++) acc[i][j][e] = 0.f;

    const __half* gAh = Ah + (size_t)(m0 + lrow) * K + lcol;
    const __half* gBh = Bh + (size_t)(n0 + lrow) * K + lcol;

    uint4 pah[2], pbh[2];
    #define LD8(kt) do { \
        pah[0] = *(const uint4*)(gAh + (kt));     pah[1] = *(const uint4*)(gAh + (kt) + 8); \
        pbh[0] = *(const uint4*)(gBh + (kt));     pbh[1] = *(const uint4*)(gBh + (kt) + 8); \
    } while (0)

    LD8(0);

    const uint32_t* A32h = (const uint32_t*)sAh;
    const uint32_t* B32h = (const uint32_t*)sBh;

    for (int kt = 0; kt < K; kt += 32) {
        *(uint4*)(sAh + lrow * 40 + lcol) = pah[0]; *(uint4*)(sAh + lrow * 40 + lcol + 8) = pah[1];
        *(uint4*)(sBh + lrow * 40 + lcol) = pbh[0]; *(uint4*)(sBh + lrow * 40 + lcol + 8) = pbh[1];
        __syncthreads();
        if (kt + 32 < K) LD8(kt + 32);

        #pragma unroll
        for (int ks = 0; ks < 2; ks++) {
            uint32_t fah[4][4];
            #pragma unroll
            for (int i = 0; i < 4; i++) {
                int r = (wm + i * 16 + g) * 20 + ks * 8 + tg;
                int r8 = r + 160;
                fah[i][0] = A32h[r]; fah[i][1] = A32h[r8]; fah[i][2] = A32h[r + 4]; fah[i][3] = A32h[r8 + 4];
            }
            #pragma unroll
            for (int j = 0; j < 4; j++) {
                int nb = (wn + j * 8 + g) * 20 + ks * 8 + tg;
                uint32_t bh0 = B32h[nb], bh1 = B32h[nb + 4];
                #pragma unroll
                for (int i = 0; i < 4; i++)
                    mma_f16(acc[i][j], fah[i][0], fah[i][1], fah[i][2], fah[i][3], bh0, bh1);
            }
        }
        __syncthreads();
    }
    #undef LD8

    if (OUT16) {
        // ---- fused RoPE on q/k columns ----
        const float SC2 = 1.4426950408889634f * 0.10206207261596575f;  // log2e/sqrt(96)
        const int col32 = n0 + wn;             // warp's 32-col block base
        const int head  = col32 / 96;
        const int chunk = (col32 % 96) / 32;   // 0:t  1:h  2:w
        const bool rope = (head < 20);
        const float qs  = (head < 16) ? SC2 : 1.f;

        #pragma unroll
        for (int i = 0; i < 4; i++) {
            if (rope) {
                int r0 = m0 + wm + i * 16 + g;
                int r1 = r0 + 8;
                int pos0 = (chunk == 0) ? ((r0 >> 8) & 31) : (chunk == 1 ? 32 + ((r0 >> 4) & 15) : 48 + (r0 & 15));
                int pos1 = (chunk == 0) ? ((r1 >> 8) & 31) : (chunk == 1 ? 32 + ((r1 >> 4) & 15) : 48 + (r1 & 15));
                #pragma unroll
                for (int jp = 0; jp < 2; jp++) {           // pair (jp, jp+2)
                    int fbase = jp * 8 + 2 * tg;           // freq of element col
                    #pragma unroll
                    for (int e = 0; e < 4; e++) {
                        int f   = fbase + (e & 1);         // e0/e2: col 2tg ; e1/e3: col 2tg+1
                        int pos = (e < 2) ? pos0 : pos1;   // e0/e1: row r0 ; e2/e3: row r1
                        float c = g_cos[pos * 16 + f];
                        float s = g_sin[pos * 16 + f];
                        float x1 = acc[i][jp][e];
                        float x2 = acc[i][jp + 2][e];
                        acc[i][jp][e]     = (x1 * c - x2 * s) * qs;
                        acc[i][jp + 2][e] = (x2 * c + x1 * s) * qs;
                    }
                }
            }
            #pragma unroll
            for (int j = 0; j < 4; j++) {
                int row = m0 + wm + i * 16 + g;
                int col = n0 + wn + j * 8 + 2 * tg;
                *(uint32_t*)(Ch + (size_t)row * N + col)       = packh2(acc[i][j][0], acc[i][j][1]);
                *(uint32_t*)(Ch + (size_t)(row + 8) * N + col) = packh2(acc[i][j][2], acc[i][j][3]);
            }
        }
    } else {
        #pragma unroll
        for (int i = 0; i < 4; i++)
            #pragma unroll
            for (int j = 0; j < 4; j++) {
                int row = m0 + wm + i * 16 + g;
                int col = n0 + wn + j * 8 + 2 * tg;
                *(float2*)(C + (size_t)row * N + col)       = make_float2(acc[i][j][0], acc[i][j][1]);
                *(float2*)(C + (size_t)(row + 8) * N + col) = make_float2(acc[i][j][2], acc[i][j][3]);
            }
    }
}

// ---------------------------------------------------------------------------
// Attention: CTA = (b,t,head,64-query tile), 128 threads (4 warps x 16 rows).
// Flash-style, no-max f32 ex2 softmax, pure fp16 matmuls (f32 accum):
//   scores = Qh*Kh ;  out = Ph*Vh.
// ---------------------------------------------------------------------------
__global__ __launch_bounds__(128) void attn_kernel() {
    extern __shared__ __half smb[];
    __half* Qh = smb;                 // [64][120]
    __half* Kh = Qh + 7680;           // [64][120]
    __half* Vh = Kh + 7680;           // transposed [96][72]

    const int tid = threadIdx.x, warp = tid >> 5, lane = tid & 31;
    const int g = lane >> 2, tg = lane & 3;
    const int bid = blockIdx.x;
    const int qt = bid & 3, h = (bid >> 2) & 15, bt = bid >> 6, grp = h >> 2;
    const size_t tokbase = (size_t)bt * 256;

    #pragma unroll
    for (int t = 0; t < 6; t++) {
        int u = tid + t * 128;
        int row = u / 12, c8 = u % 12;
        size_t gb = (tokbase + qt * 64 + row) * QKVD + h * 96 + c8 * 8;
        *(uint4*)(Qh + row * 120 + c8 * 8) = *(const uint4*)(g_qkvh + gb);
    }

    const uint32_t* Q32 = (const uint32_t*)Qh;
    const uint32_t* K32 = (const uint32_t*)Kh;
    const uint32_t* V32 = (const uint32_t*)Vh;

    float acc[12][4];
    #pragma unroll
    for (int j = 0; j < 12; j++)
        #pragma unroll
        for (int e = 0; e < 4; e++) acc[j][e] = 0.f;
    float rs0 = 0.f, rs1 = 0.f;

    for (int c = 0; c < 4; c++) {
        #pragma unroll
        for (int t = 0; t < 6; t++) {
            int u = tid + t * 128;
            int row = u / 12, c8 = u % 12;
            size_t gb = (tokbase + c * 64 + row) * QKVD + 1536 + grp * 96 + c8 * 8;
            *(uint4*)(Kh + row * 120 + c8 * 8) = *(const uint4*)(g_qkvh + gb);
        }
        #pragma unroll
        for (int t = 0; t < 24; t++) {
            int u = tid + t * 128;
            int key = u / 48, d = (u % 48) * 2;
            size_t gb = (tokbase + c * 64 + key) * QKVD + 1920 + grp * 96 + d;
            __half2 ph = *(const __half2*)(g_qkvh + gb);
            Vh[d * 72 + key] = __low2half(ph);  Vh[(d + 1) * 72 + key] = __high2half(ph);
        }
        __syncthreads();

        float s[8][4];
        #pragma unroll
        for (int j = 0; j < 8; j++)
            #pragma unroll
            for (int e = 0; e < 4; e++) s[j][e] = 0.f;

        #pragma unroll
        for (int ks = 0; ks < 6; ks++) {
            int r = (warp * 16 + g) * 60 + ks * 8 + tg;
            int r8 = r + 480;
            uint32_t a0 = Q32[r], a1 = Q32[r8], a2 = Q32[r + 4], a3 = Q32[r8 + 4];
            #pragma unroll
            for (int j = 0; j < 8; j++) {
                int nb = (j * 8 + g) * 60 + ks * 8 + tg;
                uint32_t b0 = K32[nb], b1 = K32[nb + 4];
                mma_f16(s[j], a0, a1, a2, a3, b0, b1);
            }
        }

        #pragma unroll
        for (int j = 0; j < 8; j++) {
            s[j][0] = ex2f(s[j][0]); s[j][1] = ex2f(s[j][1]);
            s[j][2] = ex2f(s[j][2]); s[j][3] = ex2f(s[j][3]);
            rs0 += s[j][0] + s[j][1];
            rs1 += s[j][2] + s[j][3];
        }

        #pragma unroll
        for (int kk = 0; kk < 4; kk++) {
            uint32_t A0 = packh2(s[2 * kk][0],     s[2 * kk][1]);
            uint32_t A1 = packh2(s[2 * kk][2],     s[2 * kk][3]);
            uint32_t A2 = packh2(s[2 * kk + 1][0], s[2 * kk + 1][1]);
            uint32_t A3 = packh2(s[2 * kk + 1][2], s[2 * kk + 1][3]);
            #pragma unroll
            for (int j = 0; j < 12; j++) {
                int vb = (j * 8 + g) * 36 + kk * 8 + tg;
                uint32_t b0 = V32[vb], b1 = V32[vb + 4];
                mma_f16(acc[j], A0, A1, A2, A3, b0, b1);
            }
        }
        __syncthreads();
    }

    rs0 += __shfl_xor_sync(0xffffffffu, rs0, 1);
    rs0 += __shfl_xor_sync(0xffffffffu, rs0, 2);
    rs1 += __shfl_xor_sync(0xffffffffu, rs1, 1);
    rs1 += __shfl_xor_sync(0xffffffffu, rs1, 2);
    float i0 = 1.f / rs0, i1 = 1.f / rs1;

    int tok0 = bt * 256 + qt * 64 + warp * 16 + g;
    #pragma unroll
    for (int j = 0; j < 12; j++) {
        int col = h * 96 + j * 8 + 2 * tg;
        *(uint32_t*)(g_ath + (size_t)tok0 * DM + col)       = packh2(acc[j][0] * i0, acc[j][1] * i0);
        *(uint32_t*)(g_ath + (size_t)(tok0 + 8) * DM + col) = packh2(acc[j][2] * i1, acc[j][3] * i1);
    }
}

// ---------------------------------------------------------------------------
extern "C" void kernel_launch(void* const* d_in, const int* in_sizes, int n_in,
                              void* d_out, int out_size) {
    (void)in_sizes; (void)n_in; (void)out_size;
    const float* x     = (const float*)d_in[0];
    const float* w_qkv = (const float*)d_in[2];
    const float* w_o   = (const float*)d_in[3];
    float* out = (float*)d_out;

    __half *xh, *wqh, *woh, *qkvh, *ath;
    cudaGetSymbolAddress((void**)&xh, g_xh);
    cudaGetSymbolAddress((void**)&wqh, g_wqh);
    cudaGetSymbolAddress((void**)&woh, g_woh);
    cudaGetSymbolAddress((void**)&qkvh, g_qkvh);
    cudaGetSymbolAddress((void**)&ath, g_ath);

    cudaFuncSetAttribute(attn_kernel, cudaFuncAttributeMaxDynamicSharedMemorySize, 44544);

    rope_table_kernel<<<1, 1024>>>();
    cvt_kernel<<<24576, 256>>>((const float4*)x,     (uint32_t*)xh,  6291456);
    cvt_kernel<<<3456,  256>>>((const float4*)w_qkv, (uint32_t*)wqh, 884736);
    cvt_kernel<<<2304,  256>>>((const float4*)w_o,   (uint32_t*)woh, 589824);

    dim3 g1(QKVD / 128, NTOK / 128);
    gemm_h1<1><<<g1, 256>>>(xh, wqh, nullptr, qkvh, NTOK, QKVD, DM);

    attn_kernel<<<4096, 128, 44544>>>();

    dim3 g2(DM / 128, NTOK / 128);
    gemm_h1<0><<<g2, 256>>>(ath, woh, out, nullptr, NTOK, DM, DM);
}